// round 15
// baseline (speedup 1.0000x reference)
#include <cuda_runtime.h>
#include <cuda_bf16.h>
#include <cuda_fp16.h>
#include <cstdint>

#define NN 100000
#define NE 1600000
#define NG 512
#define DIM 128
#define NC 10

// ---------------- scratch (device globals) ------------------------------------
__device__ int            g_is64;
__device__ int            g_total;
__device__ int            g_deg[NN];
__device__ float          g_dinv[NN];
__device__ int            g_off[NN];
__device__ int            g_pos[NN];
__device__ int            g_src[NE];
__device__ __half2        g_xw16[(size_t)NN * 64];   // GEMM output, fp16 (gathered)
__device__ __half2        g_h16[(size_t)NN * 64];    // agg output, fp16
__device__ unsigned short g_wb[2][16384];            // [layer][n*128+k]  B=W^T fp16

__device__ __forceinline__ int idx_at(const void* p, long long i, int is64) {
    return is64 ? (int)((const long long*)p)[i] : ((const int*)p)[i];
}
__device__ __forceinline__ unsigned short f16bits(float v) {
    __half h = __float2half_rn(v);
    return *reinterpret_cast<unsigned short*>(&h);
}
__device__ __forceinline__ uint32_t h2u(__half2 h) {
    return *reinterpret_cast<uint32_t*>(&h);
}
__device__ __forceinline__ uint32_t smem_u32(const void* p) {
    uint32_t a;
    asm("{ .reg .u64 t; cvta.to.shared.u64 t, %1; cvt.u32.u64 %0, t; }" : "=r"(a) : "l"(p));
    return a;
}

#define LDSM4(r0, r1, r2, r3, addr)                                         \
    asm volatile("ldmatrix.sync.aligned.m8n8.x4.shared.b16 {%0,%1,%2,%3}, [%4];" \
                 : "=r"(r0), "=r"(r1), "=r"(r2), "=r"(r3) : "r"(addr))

#define MMA_F16(d, a0, a1, a2, a3, b0, b1)                                   \
    asm volatile("mma.sync.aligned.m16n8k16.row.col.f32.f16.f16.f32 "        \
                 "{%0,%1,%2,%3},{%4,%5,%6,%7},{%8,%9},{%0,%1,%2,%3};"        \
                 : "+f"(d[0]), "+f"(d[1]), "+f"(d[2]), "+f"(d[3])            \
                 : "r"(a0), "r"(a1), "r"(a2), "r"(a3), "r"(b0), "r"(b1))

// ---------------- setup (zero + dtype probe) ----------------------------------
__global__ void k_zero(const void* ei) {
    if (blockIdx.x == 0 && threadIdx.x == 0) {
        const int* w = (const int*)ei;
        int nz = 0;
        for (int i = 0; i < 128; ++i) nz += (w[2 * i + 1] != 0);
        g_is64 = (nz == 0) ? 1 : 0;
        g_total = 0;
    }
    int i = blockIdx.x * blockDim.x + threadIdx.x;
    int stride = gridDim.x * blockDim.x;
    for (int j = i; j < NN; j += stride) g_deg[j] = 0;
}

// W[k][n] -> B[n][k] fp16 for both layers
__global__ void k_wprep(const float* __restrict__ W1, const float* __restrict__ W2) {
    int i = blockIdx.x * blockDim.x + threadIdx.x;
    int stride = gridDim.x * blockDim.x;
    for (int e = i; e < 2 * 16384; e += stride) {
        int l = e >> 14;
        int idx = e & 16383;
        int nrow = idx >> 7, k = idx & 127;
        const float* W = l ? W2 : W1;
        g_wb[l][idx] = f16bits(W[k * 128 + nrow]);
    }
}

__global__ void k_hist(const void* __restrict__ ei) {
    int i = blockIdx.x * blockDim.x + threadIdx.x;
    int stride = gridDim.x * blockDim.x;
    int is64 = g_is64;
    for (int e = i; e < NE; e += stride) {
        int d = idx_at(ei, (long long)NE + e, is64);
        atomicAdd(&g_deg[d], 1);
    }
}

// segment allocation: warp-scan degrees, one atomic per warp; also dinv
__global__ void k_alloc() {
    int i = blockIdx.x * blockDim.x + threadIdx.x;
    int lane = threadIdx.x & 31;
    int deg = (i < NN) ? g_deg[i] : 0;
    if (i < NN) g_dinv[i] = rsqrtf((float)(deg + 1));
    int x = deg;
#pragma unroll
    for (int d = 1; d < 32; d <<= 1) {
        int y = __shfl_up_sync(0xffffffffu, x, d);
        if (lane >= d) x += y;
    }
    int warpsum = __shfl_sync(0xffffffffu, x, 31);
    int base = 0;
    if (lane == 31) base = atomicAdd(&g_total, warpsum);
    base = __shfl_sync(0xffffffffu, base, 31);
    int start = base + x - deg;
    if (i < NN) {
        g_off[i] = start;
        g_pos[i] = start;
    }
}

__global__ void k_csr(const void* __restrict__ ei) {
    int i = blockIdx.x * blockDim.x + threadIdx.x;
    int stride = gridDim.x * blockDim.x;
    int is64 = g_is64;
    for (int e = i; e < NE; e += stride) {
        int s = idx_at(ei, e, is64);
        int d = idx_at(ei, (long long)NE + e, is64);
        int p = atomicAdd(&g_pos[d], 1);
        g_src[p] = s;
    }
}

// ---------------- fp16 tensor GEMM -> fp16 output ----------------------------
// D = A(fp16) * W(fp16). 128-row tiles, 512 threads, 16 warps in 4x4 grid,
// warp tile = 32 rows x 32 cols, full K=128 resident. smem ~70KB -> 3 CTAs/SM.
#define AST 136
#define SM_A  0
#define SM_W  34816
#define GEMM_SMEM 69632

__global__ __launch_bounds__(512, 3) void k_gemm_tc(const float* __restrict__ Aext,
                                                    int a_is_h16, int wsel, int n) {
    extern __shared__ char smem[];
    uint32_t sb = smem_u32(smem);
    int tid = threadIdx.x, wid = tid >> 5, lane = tid & 31;
    int row0 = blockIdx.x * 128;

    // ---- stage A (fp16): 128 rows x 128 k ----
    unsigned short* as = (unsigned short*)(smem + SM_A);
    if (a_is_h16) {
        for (int idx = tid; idx < 2048; idx += 512) {
            int row = idx >> 4;
            int ch = idx & 15;
            uint4 v = make_uint4(0, 0, 0, 0);
            if (row0 + row < n)
                v = ((const uint4*)g_h16)[(size_t)(row0 + row) * 16 + ch];
            *(uint4*)&as[row * AST + ch * 8] = v;
        }
    } else {
        for (int idx = tid; idx < 2048; idx += 512) {
            int row = idx >> 4;
            int ch = idx & 15;
            float4 v0 = make_float4(0.f, 0.f, 0.f, 0.f), v1 = v0;
            if (row0 + row < n) {
                const float* src = &Aext[(size_t)(row0 + row) * 128 + ch * 8];
                v0 = *(const float4*)src;
                v1 = *(const float4*)(src + 4);
            }
            uint4 o;
            o.x = h2u(__floats2half2_rn(v0.x, v0.y));
            o.y = h2u(__floats2half2_rn(v0.z, v0.w));
            o.z = h2u(__floats2half2_rn(v1.x, v1.y));
            o.w = h2u(__floats2half2_rn(v1.z, v1.w));
            *(uint4*)&as[row * AST + ch * 8] = o;
        }
    }
    // ---- stage W (128 n-rows x 128 k) ----
    {
        unsigned short* ws = (unsigned short*)(smem + SM_W);
        for (int idx = tid; idx < 2048; idx += 512) {
            int nr = idx >> 4;
            int kq = (idx & 15) * 8;
            *(uint4*)&ws[nr * AST + kq] = *(const uint4*)&g_wb[wsel][nr * 128 + kq];
        }
    }
    __syncthreads();

    // ---- mainloop: warp = 32 rows x 32 cols ----
    float acc[8][4];
#pragma unroll
    for (int j = 0; j < 8; ++j)
#pragma unroll
        for (int q = 0; q < 4; ++q) acc[j][q] = 0.f;

    int wr = (wid >> 2) * 32;            // 0,32,64,96
    int wc = (wid & 3) * 32;             // 0,32,64,96
    uint32_t a_off = (uint32_t)(((wr + (lane & 15)) * AST + ((lane >> 4) << 3)) * 2);
    uint32_t b_off = (uint32_t)(((wc + (lane & 7) + ((lane >> 4) << 3)) * AST +
                                 (((lane >> 3) & 1) << 3)) * 2);
    uint32_t aA_addr = sb + SM_A + a_off;                 // rows wr..wr+15
    uint32_t aB_addr = aA_addr + 16 * AST * 2;            // rows wr+16..wr+31
    uint32_t bA_addr = sb + SM_W + b_off;                 // cols wc..wc+15
    uint32_t bB_addr = bA_addr + 16 * AST * 2;            // cols wc+16..wc+31

#pragma unroll
    for (int p = 0; p < 8; ++p) {
        uint32_t ka = p * 32;
        uint32_t a0, a1, a2, a3, a4, a5, a6, a7;
        uint32_t b0, b1, b2, b3, b4, b5, b6, b7;
        LDSM4(a0, a1, a2, a3, aA_addr + ka);
        LDSM4(a4, a5, a6, a7, aB_addr + ka);
        LDSM4(b0, b1, b2, b3, bA_addr + ka);
        LDSM4(b4, b5, b6, b7, bB_addr + ka);
        MMA_F16(acc[0], a0, a1, a2, a3, b0, b1);
        MMA_F16(acc[1], a0, a1, a2, a3, b2, b3);
        MMA_F16(acc[2], a0, a1, a2, a3, b4, b5);
        MMA_F16(acc[3], a0, a1, a2, a3, b6, b7);
        MMA_F16(acc[4], a4, a5, a6, a7, b0, b1);
        MMA_F16(acc[5], a4, a5, a6, a7, b2, b3);
        MMA_F16(acc[6], a4, a5, a6, a7, b4, b5);
        MMA_F16(acc[7], a4, a5, a6, a7, b6, b7);
    }

    // ---- epilogue: fp16 stores ----
    int rbase = row0 + wr + (lane >> 2);
    int cbase = wc + (lane & 3) * 2;
#pragma unroll
    for (int half = 0; half < 2; ++half) {
        int r0 = rbase + half * 16;
#pragma unroll
        for (int g = 0; g < 4; ++g) {
            float* a = acc[half * 4 + g];
            int c = cbase + g * 8;
            if (r0 < n)
                g_xw16[(size_t)r0 * 64 + (c >> 1)] = __floats2half2_rn(a[0], a[1]);
            if (r0 + 8 < n)
                g_xw16[(size_t)(r0 + 8) * 64 + (c >> 1)] = __floats2half2_rn(a[2], a[3]);
        }
    }
}

// ---------------- aggregation: one warp per destination node ------------------
__global__ void k_agg(const float* __restrict__ bias, int dorelu) {
    int warp = (blockIdx.x * blockDim.x + threadIdx.x) >> 5;
    if (warp >= NN) return;
    int lane = threadIdx.x & 31;
    float di = g_dinv[warp];
    const uint2* xw2 = (const uint2*)g_xw16;

    uint2 raw = xw2[(size_t)warp * 32 + lane];
    float2 f0 = __half22float2(*(__half2*)&raw.x);
    float2 f1 = __half22float2(*(__half2*)&raw.y);
    float4 acc = make_float4(f0.x * di, f0.y * di, f1.x * di, f1.y * di);

    int e0 = g_off[warp], e1 = e0 + g_deg[warp];
    for (int e = e0; e < e1; e += 32) {
        int cnt = min(32, e1 - e);
        int sidx = (lane < cnt) ? g_src[e + lane] : 0;
        float dv = (lane < cnt) ? g_dinv[sidx] : 0.f;
#pragma unroll 4
        for (int j = 0; j < cnt; ++j) {
            int s = __shfl_sync(0xffffffffu, sidx, j);
            float w = __shfl_sync(0xffffffffu, dv, j);
            uint2 r = xw2[(size_t)s * 32 + lane];
            float2 v0 = __half22float2(*(__half2*)&r.x);
            float2 v1 = __half22float2(*(__half2*)&r.y);
            acc.x += v0.x * w;
            acc.y += v0.y * w;
            acc.z += v1.x * w;
            acc.w += v1.y * w;
        }
    }
    float4 bb = ((const float4*)bias)[lane];
    acc.x = acc.x * di + bb.x;
    acc.y = acc.y * di + bb.y;
    acc.z = acc.z * di + bb.z;
    acc.w = acc.w * di + bb.w;
    if (dorelu) {
        acc.x = fmaxf(acc.x, 0.f);
        acc.y = fmaxf(acc.y, 0.f);
        acc.z = fmaxf(acc.z, 0.f);
        acc.w = fmaxf(acc.w, 0.f);
    }
    uint2 o;
    o.x = h2u(__floats2half2_rn(acc.x, acc.y));
    o.y = h2u(__floats2half2_rn(acc.z, acc.w));
    ((uint2*)g_h16)[(size_t)warp * 32 + lane] = o;
}

// ---------------- fused pool + classifier (batch is sorted) -------------------
__global__ void k_final(const void* __restrict__ batch, const float* __restrict__ Wc,
                        const float* __restrict__ bc, float* __restrict__ out) {
    __shared__ float gs[DIM];
    __shared__ int srange[2];
    int b = blockIdx.x, t = threadIdx.x;
    int is64 = g_is64;
    if (t < 2) {
        int target = b + t;     // lower_bound of target
        int lo = 0, hi = NN;
        while (lo < hi) {
            int m = (lo + hi) >> 1;
            if (idx_at(batch, m, is64) < target) lo = m + 1;
            else hi = m;
        }
        srange[t] = lo;
    }
    __syncthreads();
    int lo = srange[0], hi = srange[1];
    const __half* h = (const __half*)g_h16;
    float acc = 0.f;
    for (int i = lo; i < hi; ++i)
        acc += __half2float(h[(size_t)i * 128 + t]);
    float c = fmaxf((float)(hi - lo), 1.f);
    gs[t] = acc / c;
    __syncthreads();
    if (t < NC) {
        float s = bc[t];
#pragma unroll 16
        for (int k = 0; k < DIM; ++k) s += gs[k] * Wc[k * NC + t];
        out[b * NC + t] = s;
    }
}

// ---------------- launch -------------------------------------------------------
extern "C" void kernel_launch(void* const* d_in, const int* in_sizes, int n_in,
                              void* d_out, int out_size) {
    const float* x     = (const float*)d_in[0];
    const void*  ei    = d_in[1];
    const void*  batch = d_in[2];
    const float* W1    = (const float*)d_in[3];
    const float* b1    = (const float*)d_in[4];
    const float* W2    = (const float*)d_in[5];
    const float* b2    = (const float*)d_in[6];
    const float* Wc    = (const float*)d_in[7];
    const float* bc    = (const float*)d_in[8];
    float*       out   = (float*)d_out;

    cudaFuncSetAttribute(k_gemm_tc, cudaFuncAttributeMaxDynamicSharedMemorySize, GEMM_SMEM);

    int gemm_blocks = (NN + 127) / 128;
    int agg_blocks = (NN * 32 + 255) / 256;

    // fork: side stream runs {wprep, gemm1} concurrently with {hist, alloc, csr}
    cudaStream_t s1;
    cudaEvent_t evFork, evJoin;
    cudaStreamCreateWithFlags(&s1, cudaStreamNonBlocking);
    cudaEventCreateWithFlags(&evFork, cudaEventDisableTiming);
    cudaEventCreateWithFlags(&evJoin, cudaEventDisableTiming);

    k_zero<<<256, 256>>>(ei);
    cudaEventRecord(evFork, 0);
    cudaStreamWaitEvent(s1, evFork, 0);

    // branch A (s1): weight prep + layer-1 GEMM
    k_wprep<<<64, 256, 0, s1>>>(W1, W2);
    k_gemm_tc<<<gemm_blocks, 512, GEMM_SMEM, s1>>>(x, 0, 0, NN);
    cudaEventRecord(evJoin, s1);

    // branch B (default stream): graph structure
    k_hist<<<512, 256>>>(ei);
    k_alloc<<<(NN + 255) / 256, 256>>>();
    k_csr<<<512, 256>>>(ei);

    // join, then the serial tail
    cudaStreamWaitEvent(0, evJoin, 0);
    k_agg<<<agg_blocks, 256>>>(b1, 1);
    k_gemm_tc<<<gemm_blocks, 512, GEMM_SMEM>>>(nullptr, 1, 1, NN);
    k_agg<<<agg_blocks, 256>>>(b2, 0);
    k_final<<<NG, DIM>>>(batch, Wc, bc, out);
}

// round 16
// speedup vs baseline: 1.0206x; 1.0206x over previous
#include <cuda_runtime.h>
#include <cuda_bf16.h>
#include <cuda_fp16.h>
#include <cstdint>

#define NN 100000
#define NE 1600000
#define NG 512
#define DIM 128
#define NC 10

// ---------------- scratch (device globals) ------------------------------------
__device__ int            g_is64;
__device__ int            g_total;
__device__ int            g_deg[NN];
__device__ float          g_dinv[NN];
__device__ int            g_off[NN];
__device__ int            g_pos[NN];
__device__ int            g_src[NE];
__device__ __half2        g_xw16[(size_t)NN * 64];   // GEMM output, fp16 (gathered)
__device__ __half2        g_h16[(size_t)NN * 64];    // agg output, fp16
__device__ unsigned short g_wb[2][16384];            // [layer][n*128+k]  B=W^T fp16

__device__ __forceinline__ int idx_at(const void* p, long long i, int is64) {
    return is64 ? (int)((const long long*)p)[i] : ((const int*)p)[i];
}
__device__ __forceinline__ unsigned short f16bits(float v) {
    __half h = __float2half_rn(v);
    return *reinterpret_cast<unsigned short*>(&h);
}
__device__ __forceinline__ uint32_t h2u(__half2 h) {
    return *reinterpret_cast<uint32_t*>(&h);
}
__device__ __forceinline__ uint32_t smem_u32(const void* p) {
    uint32_t a;
    asm("{ .reg .u64 t; cvta.to.shared.u64 t, %1; cvt.u32.u64 %0, t; }" : "=r"(a) : "l"(p));
    return a;
}

#define LDSM4(r0, r1, r2, r3, addr)                                         \
    asm volatile("ldmatrix.sync.aligned.m8n8.x4.shared.b16 {%0,%1,%2,%3}, [%4];" \
                 : "=r"(r0), "=r"(r1), "=r"(r2), "=r"(r3) : "r"(addr))

#define MMA_F16(d, a0, a1, a2, a3, b0, b1)                                   \
    asm volatile("mma.sync.aligned.m16n8k16.row.col.f32.f16.f16.f32 "        \
                 "{%0,%1,%2,%3},{%4,%5,%6,%7},{%8,%9},{%0,%1,%2,%3};"        \
                 : "+f"(d[0]), "+f"(d[1]), "+f"(d[2]), "+f"(d[3])            \
                 : "r"(a0), "r"(a1), "r"(a2), "r"(a3), "r"(b0), "r"(b1))

// ---------------- setup (zero + dtype probe) ----------------------------------
__global__ void k_zero(const void* ei) {
    if (blockIdx.x == 0 && threadIdx.x == 0) {
        const int* w = (const int*)ei;
        int nz = 0;
        for (int i = 0; i < 128; ++i) nz += (w[2 * i + 1] != 0);
        g_is64 = (nz == 0) ? 1 : 0;
        g_total = 0;
    }
    int i = blockIdx.x * blockDim.x + threadIdx.x;
    int stride = gridDim.x * blockDim.x;
    for (int j = i; j < NN; j += stride) g_deg[j] = 0;
}

// W[k][n] -> B[n][k] fp16 for both layers
__global__ void k_wprep(const float* __restrict__ W1, const float* __restrict__ W2) {
    int i = blockIdx.x * blockDim.x + threadIdx.x;
    int stride = gridDim.x * blockDim.x;
    for (int e = i; e < 2 * 16384; e += stride) {
        int l = e >> 14;
        int idx = e & 16383;
        int nrow = idx >> 7, k = idx & 127;
        const float* W = l ? W2 : W1;
        g_wb[l][idx] = f16bits(W[k * 128 + nrow]);
    }
}

__global__ void k_hist(const void* __restrict__ ei) {
    int i = blockIdx.x * blockDim.x + threadIdx.x;
    int stride = gridDim.x * blockDim.x;
    int is64 = g_is64;
    for (int e = i; e < NE; e += stride) {
        int d = idx_at(ei, (long long)NE + e, is64);
        atomicAdd(&g_deg[d], 1);
    }
}

// segment allocation: warp-scan degrees, one atomic per warp; also dinv
__global__ void k_alloc() {
    int i = blockIdx.x * blockDim.x + threadIdx.x;
    int lane = threadIdx.x & 31;
    int deg = (i < NN) ? g_deg[i] : 0;
    if (i < NN) g_dinv[i] = rsqrtf((float)(deg + 1));
    int x = deg;
#pragma unroll
    for (int d = 1; d < 32; d <<= 1) {
        int y = __shfl_up_sync(0xffffffffu, x, d);
        if (lane >= d) x += y;
    }
    int warpsum = __shfl_sync(0xffffffffu, x, 31);
    int base = 0;
    if (lane == 31) base = atomicAdd(&g_total, warpsum);
    base = __shfl_sync(0xffffffffu, base, 31);
    int start = base + x - deg;
    if (i < NN) {
        g_off[i] = start;
        g_pos[i] = start;
    }
}

__global__ void k_csr(const void* __restrict__ ei) {
    int i = blockIdx.x * blockDim.x + threadIdx.x;
    int stride = gridDim.x * blockDim.x;
    int is64 = g_is64;
    for (int e = i; e < NE; e += stride) {
        int s = idx_at(ei, e, is64);
        int d = idx_at(ei, (long long)NE + e, is64);
        int p = atomicAdd(&g_pos[d], 1);
        g_src[p] = s;
    }
}

// ---------------- fp16 tensor GEMM -> fp16 output ----------------------------
// D = A(fp16) * W(fp16). 128-row tiles, 512 threads, 16 warps in 4x4 grid,
// warp tile = 32 rows x 32 cols, full K=128 resident. smem ~70KB -> 3 CTAs/SM.
#define AST 136
#define SM_A  0
#define SM_W  34816
#define GEMM_SMEM 69632

__global__ __launch_bounds__(512, 3) void k_gemm_tc(const float* __restrict__ Aext,
                                                    int a_is_h16, int wsel, int n) {
    extern __shared__ char smem[];
    uint32_t sb = smem_u32(smem);
    int tid = threadIdx.x, wid = tid >> 5, lane = tid & 31;
    int row0 = blockIdx.x * 128;

    // ---- stage A (fp16): 128 rows x 128 k ----
    unsigned short* as = (unsigned short*)(smem + SM_A);
    if (a_is_h16) {
        for (int idx = tid; idx < 2048; idx += 512) {
            int row = idx >> 4;
            int ch = idx & 15;
            uint4 v = make_uint4(0, 0, 0, 0);
            if (row0 + row < n)
                v = ((const uint4*)g_h16)[(size_t)(row0 + row) * 16 + ch];
            *(uint4*)&as[row * AST + ch * 8] = v;
        }
    } else {
        for (int idx = tid; idx < 2048; idx += 512) {
            int row = idx >> 4;
            int ch = idx & 15;
            float4 v0 = make_float4(0.f, 0.f, 0.f, 0.f), v1 = v0;
            if (row0 + row < n) {
                const float* src = &Aext[(size_t)(row0 + row) * 128 + ch * 8];
                v0 = *(const float4*)src;
                v1 = *(const float4*)(src + 4);
            }
            uint4 o;
            o.x = h2u(__floats2half2_rn(v0.x, v0.y));
            o.y = h2u(__floats2half2_rn(v0.z, v0.w));
            o.z = h2u(__floats2half2_rn(v1.x, v1.y));
            o.w = h2u(__floats2half2_rn(v1.z, v1.w));
            *(uint4*)&as[row * AST + ch * 8] = o;
        }
    }
    // ---- stage W (128 n-rows x 128 k) ----
    {
        unsigned short* ws = (unsigned short*)(smem + SM_W);
        for (int idx = tid; idx < 2048; idx += 512) {
            int nr = idx >> 4;
            int kq = (idx & 15) * 8;
            *(uint4*)&ws[nr * AST + kq] = *(const uint4*)&g_wb[wsel][nr * 128 + kq];
        }
    }
    __syncthreads();

    // ---- mainloop: warp = 32 rows x 32 cols ----
    float acc[8][4];
#pragma unroll
    for (int j = 0; j < 8; ++j)
#pragma unroll
        for (int q = 0; q < 4; ++q) acc[j][q] = 0.f;

    int wr = (wid >> 2) * 32;            // 0,32,64,96
    int wc = (wid & 3) * 32;             // 0,32,64,96
    uint32_t a_off = (uint32_t)(((wr + (lane & 15)) * AST + ((lane >> 4) << 3)) * 2);
    uint32_t b_off = (uint32_t)(((wc + (lane & 7) + ((lane >> 4) << 3)) * AST +
                                 (((lane >> 3) & 1) << 3)) * 2);
    uint32_t aA_addr = sb + SM_A + a_off;                 // rows wr..wr+15
    uint32_t aB_addr = aA_addr + 16 * AST * 2;            // rows wr+16..wr+31
    uint32_t bA_addr = sb + SM_W + b_off;                 // cols wc..wc+15
    uint32_t bB_addr = bA_addr + 16 * AST * 2;            // cols wc+16..wc+31

#pragma unroll
    for (int p = 0; p < 8; ++p) {
        uint32_t ka = p * 32;
        uint32_t a0, a1, a2, a3, a4, a5, a6, a7;
        uint32_t b0, b1, b2, b3, b4, b5, b6, b7;
        LDSM4(a0, a1, a2, a3, aA_addr + ka);
        LDSM4(a4, a5, a6, a7, aB_addr + ka);
        LDSM4(b0, b1, b2, b3, bA_addr + ka);
        LDSM4(b4, b5, b6, b7, bB_addr + ka);
        MMA_F16(acc[0], a0, a1, a2, a3, b0, b1);
        MMA_F16(acc[1], a0, a1, a2, a3, b2, b3);
        MMA_F16(acc[2], a0, a1, a2, a3, b4, b5);
        MMA_F16(acc[3], a0, a1, a2, a3, b6, b7);
        MMA_F16(acc[4], a4, a5, a6, a7, b0, b1);
        MMA_F16(acc[5], a4, a5, a6, a7, b2, b3);
        MMA_F16(acc[6], a4, a5, a6, a7, b4, b5);
        MMA_F16(acc[7], a4, a5, a6, a7, b6, b7);
    }

    // ---- epilogue: fp16 stores ----
    int rbase = row0 + wr + (lane >> 2);
    int cbase = wc + (lane & 3) * 2;
#pragma unroll
    for (int half = 0; half < 2; ++half) {
        int r0 = rbase + half * 16;
#pragma unroll
        for (int g = 0; g < 4; ++g) {
            float* a = acc[half * 4 + g];
            int c = cbase + g * 8;
            if (r0 < n)
                g_xw16[(size_t)r0 * 64 + (c >> 1)] = __floats2half2_rn(a[0], a[1]);
            if (r0 + 8 < n)
                g_xw16[(size_t)(r0 + 8) * 64 + (c >> 1)] = __floats2half2_rn(a[2], a[3]);
        }
    }
}

// ---------------- aggregation: one warp per destination node ------------------
__global__ void k_agg(const float* __restrict__ bias, int dorelu) {
    int warp = (blockIdx.x * blockDim.x + threadIdx.x) >> 5;
    if (warp >= NN) return;
    int lane = threadIdx.x & 31;
    float di = g_dinv[warp];
    const uint2* xw2 = (const uint2*)g_xw16;

    uint2 raw = xw2[(size_t)warp * 32 + lane];
    float2 f0 = __half22float2(*(__half2*)&raw.x);
    float2 f1 = __half22float2(*(__half2*)&raw.y);
    float4 acc = make_float4(f0.x * di, f0.y * di, f1.x * di, f1.y * di);

    int e0 = g_off[warp], e1 = e0 + g_deg[warp];
    for (int e = e0; e < e1; e += 32) {
        int cnt = min(32, e1 - e);
        int sidx = (lane < cnt) ? g_src[e + lane] : 0;
        float dv = (lane < cnt) ? g_dinv[sidx] : 0.f;
#pragma unroll 4
        for (int j = 0; j < cnt; ++j) {
            int s = __shfl_sync(0xffffffffu, sidx, j);
            float w = __shfl_sync(0xffffffffu, dv, j);
            uint2 r = xw2[(size_t)s * 32 + lane];
            float2 v0 = __half22float2(*(__half2*)&r.x);
            float2 v1 = __half22float2(*(__half2*)&r.y);
            acc.x += v0.x * w;
            acc.y += v0.y * w;
            acc.z += v1.x * w;
            acc.w += v1.y * w;
        }
    }
    float4 bb = ((const float4*)bias)[lane];
    acc.x = acc.x * di + bb.x;
    acc.y = acc.y * di + bb.y;
    acc.z = acc.z * di + bb.z;
    acc.w = acc.w * di + bb.w;
    if (dorelu) {
        acc.x = fmaxf(acc.x, 0.f);
        acc.y = fmaxf(acc.y, 0.f);
        acc.z = fmaxf(acc.z, 0.f);
        acc.w = fmaxf(acc.w, 0.f);
    }
    uint2 o;
    o.x = h2u(__floats2half2_rn(acc.x, acc.y));
    o.y = h2u(__floats2half2_rn(acc.z, acc.w));
    ((uint2*)g_h16)[(size_t)warp * 32 + lane] = o;
}

// ---------------- fused pool + classifier (batch is sorted) -------------------
__global__ void k_final(const void* __restrict__ batch, const float* __restrict__ Wc,
                        const float* __restrict__ bc, float* __restrict__ out) {
    __shared__ float gs[DIM];
    __shared__ int srange[2];
    int b = blockIdx.x, t = threadIdx.x;
    int is64 = g_is64;
    if (t < 2) {
        int target = b + t;     // lower_bound of target
        int lo = 0, hi = NN;
        while (lo < hi) {
            int m = (lo + hi) >> 1;
            if (idx_at(batch, m, is64) < target) lo = m + 1;
            else hi = m;
        }
        srange[t] = lo;
    }
    __syncthreads();
    int lo = srange[0], hi = srange[1];
    const __half* h = (const __half*)g_h16;
    float acc = 0.f;
    for (int i = lo; i < hi; ++i)
        acc += __half2float(h[(size_t)i * 128 + t]);
    float c = fmaxf((float)(hi - lo), 1.f);
    gs[t] = acc / c;
    __syncthreads();
    if (t < NC) {
        float s = bc[t];
#pragma unroll 16
        for (int k = 0; k < DIM; ++k) s += gs[k] * Wc[k * NC + t];
        out[b * NC + t] = s;
    }
}

// ---------------- launch (single stream, R14 structure) ------------------------
extern "C" void kernel_launch(void* const* d_in, const int* in_sizes, int n_in,
                              void* d_out, int out_size) {
    const float* x     = (const float*)d_in[0];
    const void*  ei    = d_in[1];
    const void*  batch = d_in[2];
    const float* W1    = (const float*)d_in[3];
    const float* b1    = (const float*)d_in[4];
    const float* W2    = (const float*)d_in[5];
    const float* b2    = (const float*)d_in[6];
    const float* Wc    = (const float*)d_in[7];
    const float* bc    = (const float*)d_in[8];
    float*       out   = (float*)d_out;

    cudaFuncSetAttribute(k_gemm_tc, cudaFuncAttributeMaxDynamicSharedMemorySize, GEMM_SMEM);

    int gemm_blocks = (NN + 127) / 128;
    int agg_blocks = (NN * 32 + 255) / 256;

    k_zero<<<256, 256>>>(ei);                                      // 0 (incl. probe)
    k_wprep<<<64, 256>>>(W1, W2);                                  // 1
    k_hist<<<512, 256>>>(ei);                                      // 2
    k_gemm_tc<<<gemm_blocks, 512, GEMM_SMEM>>>(x, 0, 0, NN);       // 3 <- profiled
    k_alloc<<<(NN + 255) / 256, 256>>>();                          // 4
    k_csr<<<512, 256>>>(ei);                                       // 5
    k_agg<<<agg_blocks, 256>>>(b1, 1);                             // 6
    k_gemm_tc<<<gemm_blocks, 512, GEMM_SMEM>>>(nullptr, 1, 1, NN); // 7
    k_agg<<<agg_blocks, 256>>>(b2, 0);                             // 8
    k_final<<<NG, DIM>>>(batch, Wc, bc, out);                      // 9
}

// round 17
// speedup vs baseline: 1.3918x; 1.3637x over previous
#include <cuda_runtime.h>
#include <cuda_bf16.h>
#include <cuda_fp16.h>
#include <cstdint>

#define NN 100000
#define NE 1600000
#define NG 512
#define DIM 128
#define NC 10

// ---------------- scratch (device globals) ------------------------------------
__device__ int            g_is64;
__device__ int            g_total;
__device__ int            g_deg[NN];
__device__ float          g_dinv[NN];
__device__ int            g_off[NN];
__device__ int            g_pos[NN];
__device__ int            g_src[NE];
__device__ __half2        g_xw16[(size_t)NN * 64];   // GEMM output, fp16 (gathered)
__device__ __half2        g_h16[(size_t)NN * 64];    // agg output, fp16
__device__ unsigned short g_wb[2][16384];            // [layer][n*128+k]  B=W^T fp16

__device__ __forceinline__ int idx_at(const void* p, long long i, int is64) {
    return is64 ? (int)((const long long*)p)[i] : ((const int*)p)[i];
}
__device__ __forceinline__ unsigned short f16bits(float v) {
    __half h = __float2half_rn(v);
    return *reinterpret_cast<unsigned short*>(&h);
}
__device__ __forceinline__ uint32_t h2u(__half2 h) {
    return *reinterpret_cast<uint32_t*>(&h);
}
__device__ __forceinline__ __half2 u2h(uint32_t u) {
    return *reinterpret_cast<__half2*>(&u);
}
__device__ __forceinline__ uint32_t smem_u32(const void* p) {
    uint32_t a;
    asm("{ .reg .u64 t; cvta.to.shared.u64 t, %1; cvt.u32.u64 %0, t; }" : "=r"(a) : "l"(p));
    return a;
}

#define LDSM4(r0, r1, r2, r3, addr)                                         \
    asm volatile("ldmatrix.sync.aligned.m8n8.x4.shared.b16 {%0,%1,%2,%3}, [%4];" \
                 : "=r"(r0), "=r"(r1), "=r"(r2), "=r"(r3) : "r"(addr))

#define MMA_F16(d, a0, a1, a2, a3, b0, b1)                                   \
    asm volatile("mma.sync.aligned.m16n8k16.row.col.f32.f16.f16.f32 "        \
                 "{%0,%1,%2,%3},{%4,%5,%6,%7},{%8,%9},{%0,%1,%2,%3};"        \
                 : "+f"(d[0]), "+f"(d[1]), "+f"(d[2]), "+f"(d[3])            \
                 : "r"(a0), "r"(a1), "r"(a2), "r"(a3), "r"(b0), "r"(b1))

// ---------------- setup (zero + dtype probe) ----------------------------------
__global__ void k_zero(const void* ei) {
    if (blockIdx.x == 0 && threadIdx.x == 0) {
        const int* w = (const int*)ei;
        int nz = 0;
        for (int i = 0; i < 128; ++i) nz += (w[2 * i + 1] != 0);
        g_is64 = (nz == 0) ? 1 : 0;
        g_total = 0;
    }
    int i = blockIdx.x * blockDim.x + threadIdx.x;
    int stride = gridDim.x * blockDim.x;
    for (int j = i; j < NN; j += stride) g_deg[j] = 0;
}

// W[k][n] -> B[n][k] fp16 for both layers
__global__ void k_wprep(const float* __restrict__ W1, const float* __restrict__ W2) {
    int i = blockIdx.x * blockDim.x + threadIdx.x;
    int stride = gridDim.x * blockDim.x;
    for (int e = i; e < 2 * 16384; e += stride) {
        int l = e >> 14;
        int idx = e & 16383;
        int nrow = idx >> 7, k = idx & 127;
        const float* W = l ? W2 : W1;
        g_wb[l][idx] = f16bits(W[k * 128 + nrow]);
    }
}

__global__ void k_hist(const void* __restrict__ ei) {
    int i = blockIdx.x * blockDim.x + threadIdx.x;
    int stride = gridDim.x * blockDim.x;
    int is64 = g_is64;
    for (int e = i; e < NE; e += stride) {
        int d = idx_at(ei, (long long)NE + e, is64);
        atomicAdd(&g_deg[d], 1);
    }
}

// segment allocation: warp-scan degrees, one atomic per warp; also dinv
__global__ void k_alloc() {
    int i = blockIdx.x * blockDim.x + threadIdx.x;
    int lane = threadIdx.x & 31;
    int deg = (i < NN) ? g_deg[i] : 0;
    if (i < NN) g_dinv[i] = rsqrtf((float)(deg + 1));
    int x = deg;
#pragma unroll
    for (int d = 1; d < 32; d <<= 1) {
        int y = __shfl_up_sync(0xffffffffu, x, d);
        if (lane >= d) x += y;
    }
    int warpsum = __shfl_sync(0xffffffffu, x, 31);
    int base = 0;
    if (lane == 31) base = atomicAdd(&g_total, warpsum);
    base = __shfl_sync(0xffffffffu, base, 31);
    int start = base + x - deg;
    if (i < NN) {
        g_off[i] = start;
        g_pos[i] = start;
    }
}

__global__ void k_csr(const void* __restrict__ ei) {
    int i = blockIdx.x * blockDim.x + threadIdx.x;
    int stride = gridDim.x * blockDim.x;
    int is64 = g_is64;
    for (int e = i; e < NE; e += stride) {
        int s = idx_at(ei, e, is64);
        int d = idx_at(ei, (long long)NE + e, is64);
        int p = atomicAdd(&g_pos[d], 1);
        g_src[p] = s;
    }
}

// ---------------- fp16 tensor GEMM -> fp16 output (R14-proven shape) ----------
// D = A(fp16) * W(fp16).  64-row tiles, 512 threads (16 warps in 2x8 grid),
// warp tile = 32 rows x 16 cols, full K=128 resident. smem 52KB -> 4 CTAs/SM.
#define AST 136
#define SM_A  0
#define SM_W  17408
#define GEMM_SMEM 52224

__global__ __launch_bounds__(512, 4) void k_gemm_tc(const float* __restrict__ Aext,
                                                    int a_is_h16, int wsel, int n) {
    extern __shared__ char smem[];
    uint32_t sb = smem_u32(smem);
    int tid = threadIdx.x, wid = tid >> 5, lane = tid & 31;
    int row0 = blockIdx.x * 64;

    // ---- stage A (fp16): 64 rows x 128 k ----
    unsigned short* as = (unsigned short*)(smem + SM_A);
    if (a_is_h16) {
        for (int idx = tid; idx < 1024; idx += 512) {
            int row = idx >> 4;
            int ch = idx & 15;
            uint4 v = make_uint4(0, 0, 0, 0);
            if (row0 + row < n)
                v = ((const uint4*)g_h16)[(size_t)(row0 + row) * 16 + ch];
            *(uint4*)&as[row * AST + ch * 8] = v;
        }
    } else {
        for (int idx = tid; idx < 1024; idx += 512) {
            int row = idx >> 4;
            int ch = idx & 15;
            float4 v0 = make_float4(0.f, 0.f, 0.f, 0.f), v1 = v0;
            if (row0 + row < n) {
                const float* src = &Aext[(size_t)(row0 + row) * 128 + ch * 8];
                v0 = *(const float4*)src;
                v1 = *(const float4*)(src + 4);
            }
            uint4 o;
            o.x = h2u(__floats2half2_rn(v0.x, v0.y));
            o.y = h2u(__floats2half2_rn(v0.z, v0.w));
            o.z = h2u(__floats2half2_rn(v1.x, v1.y));
            o.w = h2u(__floats2half2_rn(v1.z, v1.w));
            *(uint4*)&as[row * AST + ch * 8] = o;
        }
    }
    // ---- stage W (128 n-rows x 128 k) ----
    {
        unsigned short* ws = (unsigned short*)(smem + SM_W);
        for (int idx = tid; idx < 2048; idx += 512) {
            int nr = idx >> 4;
            int kq = (idx & 15) * 8;
            *(uint4*)&ws[nr * AST + kq] = *(const uint4*)&g_wb[wsel][nr * 128 + kq];
        }
    }
    __syncthreads();

    // ---- mainloop: warp = 32 rows x 16 cols ----
    float acc[4][4];
#pragma unroll
    for (int j = 0; j < 4; ++j)
#pragma unroll
        for (int q = 0; q < 4; ++q) acc[j][q] = 0.f;

    int wr = (wid >> 3) * 32;            // 0 or 32
    int wc = (wid & 7) * 16;             // 0..112
    uint32_t a_off = (uint32_t)(((wr + (lane & 15)) * AST + ((lane >> 4) << 3)) * 2);
    uint32_t b_off = (uint32_t)(((wc + (lane & 7) + ((lane >> 4) << 3)) * AST +
                                 (((lane >> 3) & 1) << 3)) * 2);
    uint32_t aA_addr = sb + SM_A + a_off;
    uint32_t aB_addr = aA_addr + 16 * AST * 2;
    uint32_t b_addr  = sb + SM_W + b_off;

#pragma unroll
    for (int p = 0; p < 8; ++p) {
        uint32_t ka = p * 32;
        uint32_t a0, a1, a2, a3, a4, a5, a6, a7;
        uint32_t b0, b1, b2, b3;
        LDSM4(a0, a1, a2, a3, aA_addr + ka);
        LDSM4(a4, a5, a6, a7, aB_addr + ka);
        LDSM4(b0, b1, b2, b3, b_addr + ka);
        MMA_F16(acc[0], a0, a1, a2, a3, b0, b1);
        MMA_F16(acc[1], a0, a1, a2, a3, b2, b3);
        MMA_F16(acc[2], a4, a5, a6, a7, b0, b1);
        MMA_F16(acc[3], a4, a5, a6, a7, b2, b3);
    }

    // ---- epilogue: fp16 stores ----
    int rbase = row0 + wr + (lane >> 2);
    int cb = wc + (lane & 3) * 2;
#pragma unroll
    for (int half = 0; half < 2; ++half) {
        int r0 = rbase + half * 16;
#pragma unroll
        for (int j = 0; j < 2; ++j) {
            float* a = acc[half * 2 + j];
            int c = cb + j * 8;
            if (r0 < n)
                g_xw16[(size_t)r0 * 64 + (c >> 1)] = __floats2half2_rn(a[0], a[1]);
            if (r0 + 8 < n)
                g_xw16[(size_t)(r0 + 8) * 64 + (c >> 1)] = __floats2half2_rn(a[2], a[3]);
        }
    }
}

// ---------------- aggregation: one warp per destination node ------------------
// fp16 gather + HFMA2 accumulate (dv pre-converted to half2), fp32 finish.
__global__ void k_agg(const float* __restrict__ bias, int dorelu) {
    int warp = (blockIdx.x * blockDim.x + threadIdx.x) >> 5;
    if (warp >= NN) return;
    int lane = threadIdx.x & 31;
    float di = g_dinv[warp];
    const uint2* xw2 = (const uint2*)g_xw16;

    // self term (half2 accumulate)
    __half2 dih = __float2half2_rn(di);
    uint2 raw = xw2[(size_t)warp * 32 + lane];
    __half2 acc0 = __hmul2(u2h(raw.x), dih);
    __half2 acc1 = __hmul2(u2h(raw.y), dih);

    int e0 = g_off[warp], e1 = e0 + g_deg[warp];
    for (int e = e0; e < e1; e += 32) {
        int cnt = min(32, e1 - e);
        int sidx = (lane < cnt) ? g_src[e + lane] : 0;
        float dvf = (lane < cnt) ? g_dinv[sidx] : 0.f;
        uint32_t dvh = h2u(__float2half2_rn(dvf));
#pragma unroll 8
        for (int j = 0; j < cnt; ++j) {
            int s = __shfl_sync(0xffffffffu, sidx, j);
            uint32_t wbits = __shfl_sync(0xffffffffu, dvh, j);
            __half2 wh = u2h(wbits);
            uint2 r = xw2[(size_t)s * 32 + lane];
            acc0 = __hfma2(u2h(r.x), wh, acc0);
            acc1 = __hfma2(u2h(r.y), wh, acc1);
        }
    }
    // fp32 finish: di * acc + bias
    float2 a0 = __half22float2(acc0);
    float2 a1 = __half22float2(acc1);
    float4 bb = ((const float4*)bias)[lane];
    float4 o;
    o.x = a0.x * di + bb.x;
    o.y = a0.y * di + bb.y;
    o.z = a1.x * di + bb.z;
    o.w = a1.y * di + bb.w;
    if (dorelu) {
        o.x = fmaxf(o.x, 0.f);
        o.y = fmaxf(o.y, 0.f);
        o.z = fmaxf(o.z, 0.f);
        o.w = fmaxf(o.w, 0.f);
    }
    uint2 st;
    st.x = h2u(__floats2half2_rn(o.x, o.y));
    st.y = h2u(__floats2half2_rn(o.z, o.w));
    ((uint2*)g_h16)[(size_t)warp * 32 + lane] = st;
}

// ---------------- fused pool + classifier (batch is sorted) -------------------
__global__ void k_final(const void* __restrict__ batch, const float* __restrict__ Wc,
                        const float* __restrict__ bc, float* __restrict__ out) {
    __shared__ float gs[DIM];
    __shared__ int srange[2];
    int b = blockIdx.x, t = threadIdx.x;
    int is64 = g_is64;
    if (t < 2) {
        int target = b + t;     // lower_bound of target
        int lo = 0, hi = NN;
        while (lo < hi) {
            int m = (lo + hi) >> 1;
            if (idx_at(batch, m, is64) < target) lo = m + 1;
            else hi = m;
        }
        srange[t] = lo;
    }
    __syncthreads();
    int lo = srange[0], hi = srange[1];
    const __half* h = (const __half*)g_h16;
    float acc = 0.f;
    for (int i = lo; i < hi; ++i)
        acc += __half2float(h[(size_t)i * 128 + t]);
    float c = fmaxf((float)(hi - lo), 1.f);
    gs[t] = acc / c;
    __syncthreads();
    if (t < NC) {
        float s = bc[t];
#pragma unroll 16
        for (int k = 0; k < DIM; ++k) s += gs[k] * Wc[k * NC + t];
        out[b * NC + t] = s;
    }
}

// ---------------- launch (single stream, R14 structure) ------------------------
extern "C" void kernel_launch(void* const* d_in, const int* in_sizes, int n_in,
                              void* d_out, int out_size) {
    const float* x     = (const float*)d_in[0];
    const void*  ei    = d_in[1];
    const void*  batch = d_in[2];
    const float* W1    = (const float*)d_in[3];
    const float* b1    = (const float*)d_in[4];
    const float* W2    = (const float*)d_in[5];
    const float* b2    = (const float*)d_in[6];
    const float* Wc    = (const float*)d_in[7];
    const float* bc    = (const float*)d_in[8];
    float*       out   = (float*)d_out;

    cudaFuncSetAttribute(k_gemm_tc, cudaFuncAttributeMaxDynamicSharedMemorySize, GEMM_SMEM);

    int gemm_blocks = (NN + 63) / 64;
    int agg_blocks = (NN * 32 + 255) / 256;

    k_zero<<<256, 256>>>(ei);                                      // 0 (incl. probe)
    k_wprep<<<64, 256>>>(W1, W2);                                  // 1
    k_hist<<<512, 256>>>(ei);                                      // 2
    k_gemm_tc<<<gemm_blocks, 512, GEMM_SMEM>>>(x, 0, 0, NN);       // 3 <- profiled
    k_alloc<<<(NN + 255) / 256, 256>>>();                          // 4
    k_csr<<<512, 256>>>(ei);                                       // 5
    k_agg<<<agg_blocks, 256>>>(b1, 1);                             // 6
    k_gemm_tc<<<gemm_blocks, 512, GEMM_SMEM>>>(nullptr, 1, 1, NN); // 7
    k_agg<<<agg_blocks, 256>>>(b2, 0);                             // 8
    k_final<<<NG, DIM>>>(batch, Wc, bc, out);                      // 9
}